// round 3
// baseline (speedup 1.0000x reference)
#include <cuda_runtime.h>
#include <math.h>

#define Lc 4
#define Bc 256
#define Sc 256
#define Hc 1024
#define Kc 64
#define SPLIT 8
#define SROWS (Sc / SPLIT)   // 32

// Scratch: partial masked sums, [B][SPLIT][H] fp32 = 8 MB
__device__ float g_partial[(size_t)Bc * SPLIT * Hc];
// Arrival counters per sample (zero-initialized; each launch does exactly
// SPLIT arrivals per b and the finalizer resets to 0 -> replay-safe).
__device__ int g_count[Bc];

__device__ __forceinline__ float gelu_exact(float x) {
    return 0.5f * x * (1.0f + erff(x * 0.70710678118654752f));
}

__device__ __forceinline__ float warp_sum(float v) {
    #pragma unroll
    for (int o = 16; o; o >>= 1) v += __shfl_down_sync(0xffffffffu, v, o);
    return v;
}

// ---------------------------------------------------------------------------
// Fused kernel: grid = (SPLIT, B), 256 threads.
// Phase 1: weighted-layer pooling + masked sum over an S-chunk (DRAM-bound).
// Phase 2: the last CTA to finish a given b runs that sample's finalize,
//          overlapping with other CTAs' pooling.
// ---------------------------------------------------------------------------
__global__ __launch_bounds__(256) void fused_kernel(
    const float* __restrict__ hidden,      // [L,B,S,H]
    const int*   __restrict__ mask,        // [B,S]
    const int*   __restrict__ section_id,  // [B]
    const float* __restrict__ lw,          // [L]
    const float* __restrict__ Wd,          // [N_SEC,H,K]
    const float* __restrict__ bd,          // [N_SEC,K]
    const float* __restrict__ Wu,          // [N_SEC,K,H]
    const float* __restrict__ bu,          // [N_SEC,H]
    const float* __restrict__ Wreg,        // [H,1]
    const float* __restrict__ breg,        // [1]
    const float* __restrict__ Word,        // [H,4]
    const float* __restrict__ bord,        // [4]
    float*       __restrict__ out)         // [B] reg ++ [B,4] ord
{
    const int j = blockIdx.x;       // S-chunk
    const int b = blockIdx.y;
    const int t = threadIdx.x;      // 0..255

    // ================= Phase 1: pooling =================
    {
        float l0 = lw[0], l1 = lw[1], l2 = lw[2], l3 = lw[3];
        float mx = fmaxf(fmaxf(l0, l1), fmaxf(l2, l3));
        float w0 = expf(l0 - mx), w1 = expf(l1 - mx), w2 = expf(l2 - mx), w3 = expf(l3 - mx);
        float winv = 1.0f / (w0 + w1 + w2 + w3);
        w0 *= winv; w1 *= winv; w2 *= winv; w3 *= winv;

        __shared__ int sm[SROWS];
        if (t < SROWS) sm[t] = mask[b * Sc + j * SROWS + t];
        __syncthreads();

        const size_t LSTRIDE4 = (size_t)Bc * Sc * (Hc / 4);
        const float4* base = reinterpret_cast<const float4*>(hidden)
                           + ((size_t)b * Sc + (size_t)j * SROWS) * (Hc / 4) + t;

        float4 accA = make_float4(0.f, 0.f, 0.f, 0.f);
        float4 accB = make_float4(0.f, 0.f, 0.f, 0.f);

        #pragma unroll 2
        for (int s = 0; s < SROWS; s += 2) {
            if (sm[s]) {
                const float4* p = base + (size_t)s * (Hc / 4);
                float4 x0 = __ldcs(p);
                float4 x1 = __ldcs(p + LSTRIDE4);
                float4 x2 = __ldcs(p + 2 * LSTRIDE4);
                float4 x3 = __ldcs(p + 3 * LSTRIDE4);
                accA.x += w0 * x0.x + w1 * x1.x + w2 * x2.x + w3 * x3.x;
                accA.y += w0 * x0.y + w1 * x1.y + w2 * x2.y + w3 * x3.y;
                accA.z += w0 * x0.z + w1 * x1.z + w2 * x2.z + w3 * x3.z;
                accA.w += w0 * x0.w + w1 * x1.w + w2 * x2.w + w3 * x3.w;
            }
            if (sm[s + 1]) {
                const float4* p = base + (size_t)(s + 1) * (Hc / 4);
                float4 x0 = __ldcs(p);
                float4 x1 = __ldcs(p + LSTRIDE4);
                float4 x2 = __ldcs(p + 2 * LSTRIDE4);
                float4 x3 = __ldcs(p + 3 * LSTRIDE4);
                accB.x += w0 * x0.x + w1 * x1.x + w2 * x2.x + w3 * x3.x;
                accB.y += w0 * x0.y + w1 * x1.y + w2 * x2.y + w3 * x3.y;
                accB.z += w0 * x0.z + w1 * x1.z + w2 * x2.z + w3 * x3.z;
                accB.w += w0 * x0.w + w1 * x1.w + w2 * x2.w + w3 * x3.w;
            }
        }
        accA.x += accB.x; accA.y += accB.y; accA.z += accB.z; accA.w += accB.w;

        reinterpret_cast<float4*>(g_partial)[((size_t)b * SPLIT + j) * (Hc / 4) + t] = accA;
    }

    // ================= Arrival + election =================
    __shared__ int is_last;
    __threadfence();               // make this CTA's partial visible device-wide
    __syncthreads();
    if (t == 0) {
        int old = atomicAdd(&g_count[b], 1);
        is_last = (old == SPLIT - 1);
    }
    __syncthreads();
    if (!is_last) return;
    __threadfence();               // acquire: order subsequent reads after the atomic

    // ================= Phase 2: finalize for sample b =================
    __shared__ float4 feats4[Hc / 4];     // 4 KB
    __shared__ float4 red4[16 * 16];      // 4 KB
    __shared__ float  hk[Kc];
    __shared__ float  redm[8];
    __shared__ float  wr[5][8];
    __shared__ float  invm_s;

    const float* feats = reinterpret_cast<const float*>(feats4);

    // ---- mask count (one element per thread, S == 256) ----
    {
        float mv = (float)mask[b * Sc + t];
        mv = warp_sum(mv);
        if ((t & 31) == 0) redm[t >> 5] = mv;
        __syncthreads();
        if (t == 0) {
            float s = 0.f;
            #pragma unroll
            for (int i = 0; i < 8; i++) s += redm[i];
            invm_s = 1.0f / fmaxf(s, 1e-6f);
        }
        __syncthreads();
    }
    const float invm = invm_s;

    // ---- gather partials -> feats (L2-coherent loads) ----
    {
        const float4* pp = reinterpret_cast<const float4*>(g_partial)
                         + (size_t)b * SPLIT * (Hc / 4) + t;
        float4 a = make_float4(0.f, 0.f, 0.f, 0.f);
        #pragma unroll
        for (int jj = 0; jj < SPLIT; jj++) {
            float4 x = __ldcg(pp + jj * (Hc / 4));
            a.x += x.x; a.y += x.y; a.z += x.z; a.w += x.w;
        }
        a.x *= invm; a.y *= invm; a.z *= invm; a.w *= invm;
        feats4[t] = a;
    }
    __syncthreads();

    const int sec = section_id[b];

    // ---- down-proj: 256 threads = 16 k-quads x 16 h-groups (64 h each) ----
    {
        const int kq = t & 15;
        const int hg = t >> 4;
        const float4* wd4 = reinterpret_cast<const float4*>(Wd + (size_t)sec * Hc * Kc);
        float4 a = make_float4(0.f, 0.f, 0.f, 0.f);
        #pragma unroll 8
        for (int i = 0; i < 64; i++) {
            int h = hg * 64 + i;
            float f = feats[h];
            float4 w = __ldg(wd4 + (size_t)h * 16 + kq);
            a.x += f * w.x; a.y += f * w.y; a.z += f * w.z; a.w += f * w.w;
        }
        red4[hg * 16 + kq] = a;
    }
    __syncthreads();
    if (t < 16) {
        float4 s = make_float4(0.f, 0.f, 0.f, 0.f);
        #pragma unroll
        for (int hg = 0; hg < 16; hg++) {
            float4 x = red4[hg * 16 + t];
            s.x += x.x; s.y += x.y; s.z += x.z; s.w += x.w;
        }
        float4 bdv = __ldg(reinterpret_cast<const float4*>(bd + (size_t)sec * Kc) + t);
        hk[t * 4 + 0] = gelu_exact(s.x + bdv.x);
        hk[t * 4 + 1] = gelu_exact(s.y + bdv.y);
        hk[t * 4 + 2] = gelu_exact(s.z + bdv.z);
        hk[t * 4 + 3] = gelu_exact(s.w + bdv.w);
    }
    __syncthreads();

    // ---- up-proj residual + heads: 256 h-quads, full k sweep ----
    {
        const int c = t;   // h4 column
        const float4* wu4 = reinterpret_cast<const float4*>(Wu + (size_t)sec * Kc * Hc);
        float4 a0 = make_float4(0.f, 0.f, 0.f, 0.f);
        float4 a1 = make_float4(0.f, 0.f, 0.f, 0.f);
        #pragma unroll 8
        for (int k = 0; k < Kc; k += 2) {
            float h0 = hk[k], h1 = hk[k + 1];
            float4 w0 = __ldg(wu4 + (size_t)k * (Hc / 4) + c);
            float4 w1 = __ldg(wu4 + (size_t)(k + 1) * (Hc / 4) + c);
            a0.x += h0 * w0.x; a0.y += h0 * w0.y; a0.z += h0 * w0.z; a0.w += h0 * w0.w;
            a1.x += h1 * w1.x; a1.y += h1 * w1.y; a1.z += h1 * w1.z; a1.w += h1 * w1.w;
        }
        float4 fv  = feats4[c];
        float4 buv = __ldg(reinterpret_cast<const float4*>(bu + (size_t)sec * Hc) + c);
        float4 f2;
        f2.x = fv.x + buv.x + a0.x + a1.x;
        f2.y = fv.y + buv.y + a0.y + a1.y;
        f2.z = fv.z + buv.z + a0.z + a1.z;
        f2.w = fv.w + buv.w + a0.w + a1.w;

        float4 wrg = __ldg(reinterpret_cast<const float4*>(Wreg) + c);
        float preg = f2.x * wrg.x + f2.y * wrg.y + f2.z * wrg.z + f2.w * wrg.w;

        const float4* word4 = reinterpret_cast<const float4*>(Word);
        float4 o0 = __ldg(word4 + 4 * c + 0);
        float4 o1 = __ldg(word4 + 4 * c + 1);
        float4 o2 = __ldg(word4 + 4 * c + 2);
        float4 o3 = __ldg(word4 + 4 * c + 3);
        float po0 = f2.x * o0.x + f2.y * o1.x + f2.z * o2.x + f2.w * o3.x;
        float po1 = f2.x * o0.y + f2.y * o1.y + f2.z * o2.y + f2.w * o3.y;
        float po2 = f2.x * o0.z + f2.y * o1.z + f2.z * o2.z + f2.w * o3.z;
        float po3 = f2.x * o0.w + f2.y * o1.w + f2.z * o2.w + f2.w * o3.w;

        preg = warp_sum(preg);
        po0  = warp_sum(po0);
        po1  = warp_sum(po1);
        po2  = warp_sum(po2);
        po3  = warp_sum(po3);
        if ((t & 31) == 0) {
            int w = t >> 5;
            wr[0][w] = preg; wr[1][w] = po0; wr[2][w] = po1; wr[3][w] = po2; wr[4][w] = po3;
        }
    }
    __syncthreads();
    if (t == 0) {
        float r = 0.f, o0 = 0.f, o1 = 0.f, o2 = 0.f, o3 = 0.f;
        #pragma unroll
        for (int i = 0; i < 8; i++) {
            r  += wr[0][i]; o0 += wr[1][i]; o1 += wr[2][i]; o2 += wr[3][i]; o3 += wr[4][i];
        }
        out[b] = r + breg[0];
        float* op = out + Bc + (size_t)b * 4;
        op[0] = o0 + bord[0];
        op[1] = o1 + bord[1];
        op[2] = o2 + bord[2];
        op[3] = o3 + bord[3];
        g_count[b] = 0;   // reset for next graph replay (we are the last toucher)
    }
}

extern "C" void kernel_launch(void* const* d_in, const int* in_sizes, int n_in,
                              void* d_out, int out_size)
{
    const float* hidden = (const float*)d_in[0];
    const int*   mask   = (const int*)  d_in[1];
    const int*   sec    = (const int*)  d_in[2];
    const float* lw     = (const float*)d_in[3];
    const float* Wd     = (const float*)d_in[4];
    const float* bd     = (const float*)d_in[5];
    const float* Wu     = (const float*)d_in[6];
    const float* bu     = (const float*)d_in[7];
    const float* Wreg   = (const float*)d_in[8];
    const float* breg   = (const float*)d_in[9];
    const float* Word   = (const float*)d_in[10];
    const float* bord   = (const float*)d_in[11];
    float* out = (float*)d_out;

    dim3 grid(SPLIT, Bc);
    fused_kernel<<<grid, 256>>>(hidden, mask, sec, lw, Wd, bd, Wu, bu,
                                Wreg, breg, Word, bord, out);
}